// round 7
// baseline (speedup 1.0000x reference)
#include <cuda_runtime.h>
#include <cuda_fp16.h>
#include <math_constants.h>
#include <cstdint>

#define Ln  128
#define Bb  8
#define Dd  256
#define Hh  256
#define NHo 8
#define NGg 50
#define TJ  8
#define ROWS 64           // TJ*Bb rows per CTA

// strides (bytes unless noted)
#define H1_STRB  528      // h1/h2 fp16 row stride (264 halves); 132w%32=4 -> conflict-free
#define GA_STRB  144      // gauss/WGT fp16 row stride; 36w%32=4 -> conflict-free
#define WCH_STRB 272      // W_res K=128 chunk fp16 row stride (136 halves); 68w%32=4
#define AB_STRF  260      // AB fp32 row stride (floats); 260w%32=4
#define WO3_STRB 544      // woutT fp16 row stride (272 halves)

// smem byte offsets (total 109056 -> 2 CTAs/SM)
#define SM_H1    0                      // 64*528 = 33792
#define SM_WCH   33792                  // 256*272 = 69632 (aliases GA/WGT/AB)
#define SM_GA    (SM_WCH)               // 64*144 = 9216
#define SM_WGT   (SM_WCH + 9216)        // 256*144 = 36864 (ends 46080 <= 69632)
#define SM_AB    (SM_WCH)               // 64*260*4 = 66560 (<= 69632)
#define SM_WO3   103424                 // 8*544 = 4352
#define SM_BRES  107776                 // 1024
#define SM_DSM   108800                 // 256
#define SM_TOTAL 109056

// prep row decode boundaries
#define PR_A    (Ln*Bb)                 // 1024
#define PR_BV   (2*Ln*Bb)               // 2048
#define PR_WGT  (2*Ln*Bb + NGg)         // 2098
#define PR_CV   (2*Ln*Bb + NGg + 1)     // 2099
#define PR_TOT  (PR_CV + Hh)            // 2355

// ---- device scratch (no allocs allowed) ----
__device__ float  g_A[Ln*Bb*Hh];      // x @ W1, row j*8+b
__device__ float  g_Bv[Ln*Bb*Hh];     // x @ W2, row i*8+b
__device__ float  g_cvec[Hh];         // b_in + b_rbf @ W3
__device__ __half g_WGT[Hh*64];       // [h][g] = (W_rbf@W3)[g][h], g>=50 zero
__device__ __half g_WresT[Hh*Hh];     // [n][k] = W_res[k][n]

__device__ __forceinline__ float gelu_f(float x) {
    float u = 0.7978845608028654f * fmaf(0.044715f * x, x * x, x);
    float t;
    asm("tanh.approx.f32 %0, %1;" : "=f"(t) : "f"(u));
    return 0.5f * x * (1.0f + t);
}

__device__ __forceinline__ void mma16816(float* c, const uint32_t* a, const uint32_t* b) {
    asm volatile(
        "mma.sync.aligned.m16n8k16.row.col.f32.f16.f16.f32 "
        "{%0,%1,%2,%3}, {%4,%5,%6,%7}, {%8,%9}, {%0,%1,%2,%3};"
        : "+f"(c[0]), "+f"(c[1]), "+f"(c[2]), "+f"(c[3])
        : "r"(a[0]), "r"(a[1]), "r"(a[2]), "r"(a[3]), "r"(b[0]), "r"(b[1]));
}

// Warp GEMM block: acc[2][8] m16n8k16 frags (warp tile 32x64).
// A row-major [m][k] fp16, B [n][k] fp16.
template<int KS>
__device__ __forceinline__ void mma_block(
    const uint8_t* Abase, int astr_b, const uint8_t* Bbase, int bstr_b,
    int mrow0, int ncol0, int g, int tg, float acc[2][8][4])
{
    #pragma unroll
    for (int ks = 0; ks < KS; ks++) {
        const int k0 = ks * 16;
        uint32_t bf[8][2];
        #pragma unroll
        for (int nt = 0; nt < 8; nt++) {
            const uint8_t* bp = Bbase + (ncol0 + nt*8 + g) * bstr_b + (k0 + tg*2) * 2;
            bf[nt][0] = *(const uint32_t*)bp;
            bf[nt][1] = *(const uint32_t*)(bp + 16);
        }
        uint32_t af[2][4];
        #pragma unroll
        for (int mt = 0; mt < 2; mt++) {
            const uint8_t* ap = Abase + (mrow0 + mt*16 + g) * astr_b + (k0 + tg*2) * 2;
            af[mt][0] = *(const uint32_t*)ap;
            af[mt][1] = *(const uint32_t*)(ap + 8*astr_b);
            af[mt][2] = *(const uint32_t*)(ap + 16);
            af[mt][3] = *(const uint32_t*)(ap + 8*astr_b + 16);
        }
        #pragma unroll
        for (int mt = 0; mt < 2; mt++)
            #pragma unroll
            for (int nt = 0; nt < 8; nt++)
                mma16816(acc[mt][nt], af[mt], bf[nt]);
    }
}

// ======================= prep =======================
__global__ void __launch_bounds__(256) prep_kernel(
    const float* __restrict__ x,     const float* __restrict__ W_rbf,
    const float* __restrict__ b_rbf, const float* __restrict__ W1,
    const float* __restrict__ W2,    const float* __restrict__ W3,
    const float* __restrict__ b_in,  const float* __restrict__ W_res)
{
    const int row = blockIdx.x;
    const int h   = threadIdx.x;

    if (row >= PR_CV) {                // WresT rows: PR_CV .. PR_CV+255
        int k = row - PR_CV;
        g_WresT[h*Hh + k] = __float2half(W_res[k*Hh + h]);
        return;
    }

    __shared__ float vsm[Dd];
    const float* vec; const float* Wm;
    if (row < PR_A)        { vec = x + row*Dd;               Wm = W1; }
    else if (row < PR_BV)  { vec = x + (row - PR_A)*Dd;      Wm = W2; }
    else if (row < PR_WGT) { vec = W_rbf + (row - PR_BV)*Dd; Wm = W3; }
    else                   { vec = b_rbf;                    Wm = W3; }

    vsm[h] = vec[h];
    __syncthreads();

    float acc = 0.0f;
    #pragma unroll 8
    for (int d = 0; d < Dd; d++)
        acc = fmaf(vsm[d], Wm[d*Hh + h], acc);

    if (row < PR_A)        g_A[row*Hh + h] = acc;
    else if (row < PR_BV)  g_Bv[(row - PR_A)*Hh + h] = acc;
    else if (row < PR_WGT) g_WGT[h*64 + (row - PR_BV)] = __float2half(acc);
    else {
        g_cvec[h] = acc + b_in[h];
        #pragma unroll
        for (int g = NGg; g < 64; g++) g_WGT[h*64 + g] = __float2half(0.0f);
    }
}

// ======================= main fused HMMA kernel (2 CTAs/SM) =======================
__global__ void __launch_bounds__(256, 2) pair_kernel(
    const float* __restrict__ dist, const int* __restrict__ mask,
    const float* __restrict__ b_res, const float* __restrict__ W_out,
    const float* __restrict__ b_out, float* __restrict__ out)
{
    extern __shared__ __align__(16) uint8_t smem[];

    const int t    = threadIdx.x;
    const int wid  = t >> 5;
    const int lane = t & 31;
    const int g    = lane >> 2;
    const int tg   = lane & 3;
    const int i    = blockIdx.y;
    const int j0   = blockIdx.x * TJ;
    const int mrow0 = (wid & 1) * 32;   // warp grid 2 x 4 over 64 x 256
    const int ncol0 = (wid >> 1) * 64;

    float* bres_s = (float*)(smem + SM_BRES);
    float* dsm    = (float*)(smem + SM_DSM);

    // ---- stage small buffers + WGT + woutT(fp16) ----
    bres_s[t] = b_res[t];
    if (t < ROWS) dsm[t] = dist[i*(Ln*Bb) + j0*Bb + t];
    {
        // woutT[o][k] fp16 <- W_out[k][o]
        float4 w0 = *(const float4*)(W_out + t*NHo);
        float4 w1 = *(const float4*)(W_out + t*NHo + 4);
        __half* wo = (__half*)(smem + SM_WO3);
        wo[0*272 + t] = __float2half(w0.x);
        wo[1*272 + t] = __float2half(w0.y);
        wo[2*272 + t] = __float2half(w0.z);
        wo[3*272 + t] = __float2half(w0.w);
        wo[4*272 + t] = __float2half(w1.x);
        wo[5*272 + t] = __float2half(w1.y);
        wo[6*272 + t] = __float2half(w1.z);
        wo[7*272 + t] = __float2half(w1.w);
    }
    {
        const uint4* wgt4 = (const uint4*)g_WGT;   // 256 rows x 8 uint4
        #pragma unroll
        for (int q = 0; q < 8; q++) {
            int u = t + q*256;
            int n = u >> 3, c = u & 7;
            *(uint4*)(smem + SM_WGT + n*GA_STRB + c*16) = wgt4[u];
        }
    }
    __syncthreads();

    // ---- gaussian smearing -> GA fp16 [64][64], zero-padded k>=50 ----
    {
        const float delta = 12.0f / 49.0f;
        const float coeff = -0.5f / (delta * delta);
        #pragma unroll
        for (int q = 0; q < 8; q++) {
            int p2 = t + 256*q;            // half2 index over [64][32]
            int r = p2 >> 5, kp = p2 & 31;
            int k = 2*kp;
            float d = dsm[r];
            float v0 = 0.0f, v1 = 0.0f;
            if (k < NGg)     { float d0 = d - delta*(float)k;     v0 = __expf(coeff*d0*d0); }
            if (k+1 < NGg)   { float d1 = d - delta*(float)(k+1); v1 = __expf(coeff*d1*d1); }
            *(__half2*)(smem + SM_GA + r*GA_STRB + k*2) = __floats2half2_rn(v0, v1);
        }
    }
    __syncthreads();

    float acc[2][8][4];
    #pragma unroll
    for (int mt = 0; mt < 2; mt++)
        #pragma unroll
        for (int nt = 0; nt < 8; nt++)
            #pragma unroll
            for (int e = 0; e < 4; e++) acc[mt][nt][e] = 0.0f;

    // ---- MMA1: D1 = gauss[64x64] @ WG[64x256] (acc in regs) ----
    mma_block<4>(smem + SM_GA, GA_STRB, smem + SM_WGT, GA_STRB, mrow0, ncol0, g, tg, acc);
    __syncthreads();                       // all warps done reading GA/WGT

    // ---- stage AB = g_A(j-row) + g_Bv(i,b) + cvec (overwrites GA/WGT) ----
    #pragma unroll
    for (int q = 0; q < 16; q++) {
        int e4 = t + 256*q;                // float4 index over [64][64]
        int row = e4 >> 6;
        int col = (e4 & 63) * 4;
        float4 xa = *(const float4*)(g_A  + (size_t)(j0*Bb + row)*Hh + col);
        float4 xb = *(const float4*)(g_Bv + (size_t)(i*Bb + (row & 7))*Hh + col);
        float4 cv = *(const float4*)(g_cvec + col);
        float4 o;
        o.x = xa.x + xb.x + cv.x;
        o.y = xa.y + xb.y + cv.y;
        o.z = xa.z + xb.z + cv.z;
        o.w = xa.w + xb.w + cv.w;
        *(float4*)(smem + SM_AB + (size_t)(row*AB_STRF + col)*4) = o;
    }
    __syncthreads();

    // ---- epilogue 1 (fragment layout): h1 = gelu(D1 + AB) -> fp16 ----
    #pragma unroll
    for (int mt = 0; mt < 2; mt++) {
        const int r = mrow0 + mt*16 + g;
        #pragma unroll
        for (int nt = 0; nt < 8; nt++) {
            const int c = ncol0 + nt*8 + tg*2;
            float2 ab0 = *(const float2*)(smem + SM_AB + (size_t)(r*AB_STRF + c)*4);
            float2 ab1 = *(const float2*)(smem + SM_AB + (size_t)((r+8)*AB_STRF + c)*4);
            __half2 h0 = __floats2half2_rn(gelu_f(acc[mt][nt][0] + ab0.x),
                                           gelu_f(acc[mt][nt][1] + ab0.y));
            __half2 h1 = __floats2half2_rn(gelu_f(acc[mt][nt][2] + ab1.x),
                                           gelu_f(acc[mt][nt][3] + ab1.y));
            *(__half2*)(smem + SM_H1 + r*H1_STRB + c*2)     = h0;
            *(__half2*)(smem + SM_H1 + (r+8)*H1_STRB + c*2) = h1;
        }
    }
    __syncthreads();                       // AB reads done; h1 complete

    // ---- MMA2: D2 = h1[64x256] @ W_res[256x256], 2 K-chunks of 128 ----
    #pragma unroll
    for (int mt = 0; mt < 2; mt++)
        #pragma unroll
        for (int nt = 0; nt < 8; nt++)
            #pragma unroll
            for (int e = 0; e < 4; e++) acc[mt][nt][e] = 0.0f;

    #pragma unroll
    for (int kc = 0; kc < 2; kc++) {
        // stage W_res chunk kc: [256 n][128 k] fp16 (overwrites AB / previous chunk)
        const uint4* ws4 = (const uint4*)g_WresT;  // 256 rows x 32 uint4
        #pragma unroll
        for (int q = 0; q < 16; q++) {
            int u = t + 256*q;             // 0..4095
            int n = u >> 4, c = u & 15;
            *(uint4*)(smem + SM_WCH + n*WCH_STRB + c*16) = ws4[n*32 + kc*16 + c];
        }
        __syncthreads();
        mma_block<8>(smem + SM_H1 + kc*256, H1_STRB,
                     smem + SM_WCH, WCH_STRB, mrow0, ncol0, g, tg, acc);
        __syncthreads();                   // chunk reads done before restage
    }

    // ---- epilogue 2 (fragment, in place): h2 = h1 + gelu(D2 + b_res) -> fp16 ----
    #pragma unroll
    for (int mt = 0; mt < 2; mt++) {
        const int r = mrow0 + mt*16 + g;
        #pragma unroll
        for (int nt = 0; nt < 8; nt++) {
            const int c = ncol0 + nt*8 + tg*2;
            float2 br = *(const float2*)(bres_s + c);
            __half2* p0 = (__half2*)(smem + SM_H1 + r*H1_STRB + c*2);
            __half2* p1 = (__half2*)(smem + SM_H1 + (r+8)*H1_STRB + c*2);
            float2 f0 = __half22float2(*p0);
            float2 f1 = __half22float2(*p1);
            float n00 = f0.x + gelu_f(acc[mt][nt][0] + br.x);
            float n01 = f0.y + gelu_f(acc[mt][nt][1] + br.y);
            float n10 = f1.x + gelu_f(acc[mt][nt][2] + br.x);
            float n11 = f1.y + gelu_f(acc[mt][nt][3] + br.y);
            *p0 = __floats2half2_rn(n00, n01);
            *p1 = __floats2half2_rn(n10, n11);
        }
    }
    __syncthreads();                       // h2 complete for cross-warp reads

    // ---- phase 3 (HMMA, warps 0-3): out[64x8] = h2[64x256] @ woutT^T ----
    if (wid < 4) {
        float a3[4] = {0.0f, 0.0f, 0.0f, 0.0f};
        const int r3 = wid * 16;           // warp owns rows r3..r3+15
        #pragma unroll
        for (int ks = 0; ks < 16; ks++) {
            const int k0 = ks * 16;
            uint32_t af[4];
            const uint8_t* ap = smem + SM_H1 + (r3 + g)*H1_STRB + (k0 + tg*2)*2;
            af[0] = *(const uint32_t*)ap;
            af[1] = *(const uint32_t*)(ap + 8*H1_STRB);
            af[2] = *(const uint32_t*)(ap + 16);
            af[3] = *(const uint32_t*)(ap + 8*H1_STRB + 16);
            uint32_t bf[2];
            const uint8_t* bp = smem + SM_WO3 + g*WO3_STRB + (k0 + tg*2)*2;
            bf[0] = *(const uint32_t*)bp;
            bf[1] = *(const uint32_t*)(bp + 16);
            mma16816(a3, af, bf);
        }
        // a3: c0=(r3+g, 2tg) c1=(r3+g, 2tg+1) c2=(r3+g+8, 2tg) c3=(r3+g+8, 2tg+1)
        float2 bo = *(const float2*)(b_out + tg*2);
        #pragma unroll
        for (int h = 0; h < 2; h++) {
            const int r = r3 + g + h*8;
            const int b = r & 7;
            const int j = j0 + (r >> 3);
            bool m = (mask[b*Ln + i] != 0) && (mask[b*Ln + j] != 0);
            float v0 = a3[2*h + 0] + bo.x;
            float v1 = a3[2*h + 1] + bo.y;
            if (!m) { v0 = -CUDART_INF_F; v1 = -CUDART_INF_F; }
            size_t base = ((size_t)(b*NHo + tg*2))*(Ln*Ln) + (size_t)i*Ln + j;
            out[base]         = v0;
            out[base + Ln*Ln] = v1;
        }
    }
}

// ---------------------------------------------------------------------------
extern "C" void kernel_launch(void* const* d_in, const int* in_sizes, int n_in,
                              void* d_out, int out_size) {
    const float* x     = (const float*)d_in[0];
    const float* dist  = (const float*)d_in[1];
    const int*   mask  = (const int*)d_in[2];
    const float* W_rbf = (const float*)d_in[3];
    const float* b_rbf = (const float*)d_in[4];
    const float* W1    = (const float*)d_in[5];
    const float* W2    = (const float*)d_in[6];
    const float* W3    = (const float*)d_in[7];
    const float* b_in  = (const float*)d_in[8];
    const float* W_res = (const float*)d_in[9];
    const float* b_res = (const float*)d_in[10];
    const float* W_out = (const float*)d_in[11];
    const float* b_out = (const float*)d_in[12];
    float*       out   = (float*)d_out;

    prep_kernel<<<PR_TOT, 256>>>(x, W_rbf, b_rbf, W1, W2, W3, b_in, W_res);

    cudaFuncSetAttribute(pair_kernel, cudaFuncAttributeMaxDynamicSharedMemorySize, SM_TOTAL);
    dim3 grid(Ln / TJ, Ln);
    pair_kernel<<<grid, 256, SM_TOTAL>>>(dist, mask, b_res, W_out, b_out, out);
}

// round 8
// speedup vs baseline: 1.5265x; 1.5265x over previous
#include <cuda_runtime.h>
#include <cuda_fp16.h>
#include <math_constants.h>
#include <cstdint>

#define Ln  128
#define Bb  8
#define Dd  256
#define Hh  256
#define NHo 8
#define NGg 50
#define TJ  8
#define ROWS 64           // TJ*Bb rows per CTA

// strides (bytes). All fp16 tile strides are odd multiples of 16B -> ldmatrix conflict-free.
#define H1_STRB  528      // 33*16
#define GA_STRB  144      // 9*16
#define WCH_STRB 272      // 17*16
#define AB_STRF  260      // fp32 row stride (floats)
#define WO3_STRB 528      // 33*16 (264 halves)

// smem byte offsets (total 108928 -> 2 CTAs/SM)
#define SM_H1    0                      // 64*528 = 33792
#define SM_WCH   33792                  // 256*272 = 69632 (aliases GA/WGT/AB)
#define SM_GA    (SM_WCH)               // 64*144 = 9216
#define SM_WGT   (SM_WCH + 9216)        // 256*144 = 36864 (ends 79872 <= 103424)
#define SM_AB    (SM_WCH)               // 64*260*4 = 66560 (<= 69632)
#define SM_WO3   103424                 // 8*528 = 4224
#define SM_BRES  107648                 // 1024
#define SM_DSM   108672                 // 256
#define SM_TOTAL 108928

// prep row decode boundaries
#define PR_A    (Ln*Bb)                 // 1024
#define PR_BV   (2*Ln*Bb)               // 2048
#define PR_WGT  (2*Ln*Bb + NGg)         // 2098
#define PR_CV   (2*Ln*Bb + NGg + 1)     // 2099
#define PR_TOT  (PR_CV + Hh)            // 2355

// ---- device scratch (no allocs allowed) ----
__device__ float  g_A[Ln*Bb*Hh];      // x @ W1, row j*8+b
__device__ float  g_Bv[Ln*Bb*Hh];     // x @ W2, row i*8+b
__device__ float  g_cvec[Hh];         // b_in + b_rbf @ W3
__device__ __half g_WGT[Hh*64];       // [h][g] = (W_rbf@W3)[g][h], g>=50 zero
__device__ __half g_WresT[Hh*Hh];     // [n][k] = W_res[k][n]

__device__ __forceinline__ uint32_t smem_u32(const void* p) {
    uint32_t a;
    asm("{ .reg .u64 t; cvta.to.shared.u64 t, %1; cvt.u32.u64 %0, t; }" : "=r"(a) : "l"(p));
    return a;
}

__device__ __forceinline__ float gelu_f(float x) {
    float u = 0.7978845608028654f * fmaf(0.044715f * x, x * x, x);
    float t;
    asm("tanh.approx.f32 %0, %1;" : "=f"(t) : "f"(u));
    return 0.5f * x * (1.0f + t);
}

__device__ __forceinline__ void mma16816(float* c, const uint32_t* a, const uint32_t* b) {
    asm volatile(
        "mma.sync.aligned.m16n8k16.row.col.f32.f16.f16.f32 "
        "{%0,%1,%2,%3}, {%4,%5,%6,%7}, {%8,%9}, {%0,%1,%2,%3};"
        : "+f"(c[0]), "+f"(c[1]), "+f"(c[2]), "+f"(c[3])
        : "r"(a[0]), "r"(a[1]), "r"(a[2]), "r"(a[3]), "r"(b[0]), "r"(b[1]));
}

__device__ __forceinline__ void ldsm_x4(uint32_t* r, uint32_t addr) {
    asm volatile("ldmatrix.sync.aligned.m8n8.x4.shared.b16 {%0,%1,%2,%3}, [%4];"
                 : "=r"(r[0]), "=r"(r[1]), "=r"(r[2]), "=r"(r[3]) : "r"(addr));
}
__device__ __forceinline__ void ldsm_x2(uint32_t* r, uint32_t addr) {
    asm volatile("ldmatrix.sync.aligned.m8n8.x2.shared.b16 {%0,%1}, [%2];"
                 : "=r"(r[0]), "=r"(r[1]) : "r"(addr));
}

// Warp GEMM block with ldmatrix: acc[2][8] m16n8k16 frags (warp tile 32x64).
// A row-major [m][k] fp16, B [n][k] fp16. Both via 16x16 ldmatrix.x4 tiles:
//   lane address: row = base + (lane&15), k-halves offset = (lane>>4)*8.
// A x4 regs -> a0..a3 directly. B x4 over n-pair (nt, nt+1):
//   r0 = nt b0, r1 = nt+1 b0, r2 = nt b1, r3 = nt+1 b1.
template<int KS>
__device__ __forceinline__ void mma_block(
    uint32_t Abase, int astr_b, uint32_t Bbase, int bstr_b,
    int mrow0, int ncol0, int lane, float acc[2][8][4])
{
    const int lr = lane & 15;
    const int lcb = (lane >> 4) * 16;      // byte offset of 8-half k group
    #pragma unroll
    for (int ks = 0; ks < KS; ks++) {
        const int k0b = ks * 32;           // 16 halves = 32 bytes
        uint32_t bf[4][4];
        #pragma unroll
        for (int p = 0; p < 4; p++)
            ldsm_x4(bf[p], Bbase + (ncol0 + p*16 + lr)*bstr_b + k0b + lcb);
        uint32_t af[2][4];
        #pragma unroll
        for (int mt = 0; mt < 2; mt++)
            ldsm_x4(af[mt], Abase + (mrow0 + mt*16 + lr)*astr_b + k0b + lcb);
        #pragma unroll
        for (int mt = 0; mt < 2; mt++)
            #pragma unroll
            for (int p = 0; p < 4; p++) {
                uint32_t be[2] = {bf[p][0], bf[p][2]};
                uint32_t bo[2] = {bf[p][1], bf[p][3]};
                mma16816(acc[mt][2*p],     af[mt], be);
                mma16816(acc[mt][2*p + 1], af[mt], bo);
            }
    }
}

// ======================= prep =======================
__global__ void __launch_bounds__(256) prep_kernel(
    const float* __restrict__ x,     const float* __restrict__ W_rbf,
    const float* __restrict__ b_rbf, const float* __restrict__ W1,
    const float* __restrict__ W2,    const float* __restrict__ W3,
    const float* __restrict__ b_in,  const float* __restrict__ W_res)
{
    const int row = blockIdx.x;
    const int h   = threadIdx.x;

    if (row >= PR_CV) {                // WresT rows: PR_CV .. PR_CV+255
        int k = row - PR_CV;
        g_WresT[h*Hh + k] = __float2half(W_res[k*Hh + h]);
        return;
    }

    __shared__ float vsm[Dd];
    const float* vec; const float* Wm;
    if (row < PR_A)        { vec = x + row*Dd;               Wm = W1; }
    else if (row < PR_BV)  { vec = x + (row - PR_A)*Dd;      Wm = W2; }
    else if (row < PR_WGT) { vec = W_rbf + (row - PR_BV)*Dd; Wm = W3; }
    else                   { vec = b_rbf;                    Wm = W3; }

    vsm[h] = vec[h];
    __syncthreads();

    float acc = 0.0f;
    #pragma unroll 8
    for (int d = 0; d < Dd; d++)
        acc = fmaf(vsm[d], Wm[d*Hh + h], acc);

    if (row < PR_A)        g_A[row*Hh + h] = acc;
    else if (row < PR_BV)  g_Bv[(row - PR_A)*Hh + h] = acc;
    else if (row < PR_WGT) g_WGT[h*64 + (row - PR_BV)] = __float2half(acc);
    else {
        g_cvec[h] = acc + b_in[h];
        #pragma unroll
        for (int g = NGg; g < 64; g++) g_WGT[h*64 + g] = __float2half(0.0f);
    }
}

// ======================= main fused HMMA kernel (2 CTAs/SM, ldmatrix) =======================
__global__ void __launch_bounds__(256, 2) pair_kernel(
    const float* __restrict__ dist, const int* __restrict__ mask,
    const float* __restrict__ b_res, const float* __restrict__ W_out,
    const float* __restrict__ b_out, float* __restrict__ out)
{
    extern __shared__ __align__(16) uint8_t smem[];
    const uint32_t sb = smem_u32(smem);

    const int t    = threadIdx.x;
    const int wid  = t >> 5;
    const int lane = t & 31;
    const int g    = lane >> 2;
    const int tg   = lane & 3;
    const int i    = blockIdx.y;
    const int j0   = blockIdx.x * TJ;
    const int mrow0 = (wid & 1) * 32;   // warp grid 2 x 4 over 64 x 256
    const int ncol0 = (wid >> 1) * 64;

    float* bres_s = (float*)(smem + SM_BRES);
    float* dsm    = (float*)(smem + SM_DSM);

    // ---- stage small buffers + WGT + woutT(fp16) ----
    bres_s[t] = b_res[t];
    if (t < ROWS) dsm[t] = dist[i*(Ln*Bb) + j0*Bb + t];
    {
        // woutT[o][k] fp16 <- W_out[k][o], stride 264 halves
        float4 w0 = *(const float4*)(W_out + t*NHo);
        float4 w1 = *(const float4*)(W_out + t*NHo + 4);
        __half* wo = (__half*)(smem + SM_WO3);
        wo[0*264 + t] = __float2half(w0.x);
        wo[1*264 + t] = __float2half(w0.y);
        wo[2*264 + t] = __float2half(w0.z);
        wo[3*264 + t] = __float2half(w0.w);
        wo[4*264 + t] = __float2half(w1.x);
        wo[5*264 + t] = __float2half(w1.y);
        wo[6*264 + t] = __float2half(w1.z);
        wo[7*264 + t] = __float2half(w1.w);
    }
    {
        const uint4* wgt4 = (const uint4*)g_WGT;   // 256 rows x 8 uint4
        #pragma unroll
        for (int q = 0; q < 8; q++) {
            int u = t + q*256;
            int n = u >> 3, c = u & 7;
            *(uint4*)(smem + SM_WGT + n*GA_STRB + c*16) = wgt4[u];
        }
    }
    __syncthreads();

    // ---- gaussian smearing -> GA fp16 [64][64], zero-padded k>=50 ----
    {
        const float delta = 12.0f / 49.0f;
        const float coeff = -0.5f / (delta * delta);
        #pragma unroll
        for (int q = 0; q < 8; q++) {
            int p2 = t + 256*q;            // half2 index over [64][32]
            int r = p2 >> 5, kp = p2 & 31;
            int k = 2*kp;
            float d = dsm[r];
            float v0 = 0.0f, v1 = 0.0f;
            if (k < NGg)     { float d0 = d - delta*(float)k;     v0 = __expf(coeff*d0*d0); }
            if (k+1 < NGg)   { float d1 = d - delta*(float)(k+1); v1 = __expf(coeff*d1*d1); }
            *(__half2*)(smem + SM_GA + r*GA_STRB + k*2) = __floats2half2_rn(v0, v1);
        }
    }
    __syncthreads();

    float acc[2][8][4];
    #pragma unroll
    for (int mt = 0; mt < 2; mt++)
        #pragma unroll
        for (int nt = 0; nt < 8; nt++)
            #pragma unroll
            for (int e = 0; e < 4; e++) acc[mt][nt][e] = 0.0f;

    // ---- MMA1: D1 = gauss[64x64] @ WG[64x256] (acc in regs) ----
    mma_block<4>(sb + SM_GA, GA_STRB, sb + SM_WGT, GA_STRB, mrow0, ncol0, lane, acc);
    __syncthreads();                       // all warps done reading GA/WGT

    // ---- stage AB = g_A(j-row) + g_Bv(i,b) + cvec (overwrites GA/WGT) ----
    #pragma unroll
    for (int q = 0; q < 16; q++) {
        int e4 = t + 256*q;                // float4 index over [64][64]
        int row = e4 >> 6;
        int col = (e4 & 63) * 4;
        float4 xa = *(const float4*)(g_A  + (size_t)(j0*Bb + row)*Hh + col);
        float4 xb = *(const float4*)(g_Bv + (size_t)(i*Bb + (row & 7))*Hh + col);
        float4 cv = *(const float4*)(g_cvec + col);
        float4 o;
        o.x = xa.x + xb.x + cv.x;
        o.y = xa.y + xb.y + cv.y;
        o.z = xa.z + xb.z + cv.z;
        o.w = xa.w + xb.w + cv.w;
        *(float4*)(smem + SM_AB + (size_t)(row*AB_STRF + col)*4) = o;
    }
    __syncthreads();

    // ---- epilogue 1 (fragment layout): h1 = gelu(D1 + AB) -> fp16 ----
    #pragma unroll
    for (int mt = 0; mt < 2; mt++) {
        const int r = mrow0 + mt*16 + g;
        #pragma unroll
        for (int nt = 0; nt < 8; nt++) {
            const int c = ncol0 + nt*8 + tg*2;
            float2 ab0 = *(const float2*)(smem + SM_AB + (size_t)(r*AB_STRF + c)*4);
            float2 ab1 = *(const float2*)(smem + SM_AB + (size_t)((r+8)*AB_STRF + c)*4);
            __half2 h0 = __floats2half2_rn(gelu_f(acc[mt][nt][0] + ab0.x),
                                           gelu_f(acc[mt][nt][1] + ab0.y));
            __half2 h1 = __floats2half2_rn(gelu_f(acc[mt][nt][2] + ab1.x),
                                           gelu_f(acc[mt][nt][3] + ab1.y));
            *(__half2*)(smem + SM_H1 + r*H1_STRB + c*2)     = h0;
            *(__half2*)(smem + SM_H1 + (r+8)*H1_STRB + c*2) = h1;
        }
    }
    __syncthreads();                       // AB reads done; h1 complete

    // ---- MMA2: D2 = h1[64x256] @ W_res[256x256], 2 K-chunks of 128 ----
    #pragma unroll
    for (int mt = 0; mt < 2; mt++)
        #pragma unroll
        for (int nt = 0; nt < 8; nt++)
            #pragma unroll
            for (int e = 0; e < 4; e++) acc[mt][nt][e] = 0.0f;

    #pragma unroll
    for (int kc = 0; kc < 2; kc++) {
        // stage W_res chunk kc: [256 n][128 k] fp16 (overwrites AB / previous chunk)
        const uint4* ws4 = (const uint4*)g_WresT;  // 256 rows x 32 uint4
        #pragma unroll
        for (int q = 0; q < 16; q++) {
            int u = t + 256*q;             // 0..4095
            int n = u >> 4, c = u & 15;
            *(uint4*)(smem + SM_WCH + n*WCH_STRB + c*16) = ws4[n*32 + kc*16 + c];
        }
        __syncthreads();
        mma_block<8>(sb + SM_H1 + kc*256, H1_STRB,
                     sb + SM_WCH, WCH_STRB, mrow0, ncol0, lane, acc);
        __syncthreads();                   // chunk reads done before restage
    }

    // ---- epilogue 2 (fragment, in place): h2 = h1 + gelu(D2 + b_res) -> fp16 ----
    #pragma unroll
    for (int mt = 0; mt < 2; mt++) {
        const int r = mrow0 + mt*16 + g;
        #pragma unroll
        for (int nt = 0; nt < 8; nt++) {
            const int c = ncol0 + nt*8 + tg*2;
            float2 br = *(const float2*)(bres_s + c);
            __half2* p0 = (__half2*)(smem + SM_H1 + r*H1_STRB + c*2);
            __half2* p1 = (__half2*)(smem + SM_H1 + (r+8)*H1_STRB + c*2);
            float2 f0 = __half22float2(*p0);
            float2 f1 = __half22float2(*p1);
            float n00 = f0.x + gelu_f(acc[mt][nt][0] + br.x);
            float n01 = f0.y + gelu_f(acc[mt][nt][1] + br.y);
            float n10 = f1.x + gelu_f(acc[mt][nt][2] + br.x);
            float n11 = f1.y + gelu_f(acc[mt][nt][3] + br.y);
            *p0 = __floats2half2_rn(n00, n01);
            *p1 = __floats2half2_rn(n10, n11);
        }
    }
    __syncthreads();                       // h2 complete for cross-warp reads

    // ---- phase 3 (HMMA, warps 0-3): out[64x8] = h2[64x256] @ woutT^T ----
    if (wid < 4) {
        float a3[4] = {0.0f, 0.0f, 0.0f, 0.0f};
        const int r3 = wid * 16;           // warp owns rows r3..r3+15
        const int lr = lane & 15;
        const int lcb = (lane >> 4) * 16;
        const int br_ = lane & 7;          // B ldsm.x2 row
        const int bcb = ((lane >> 3) & 1) * 16;
        #pragma unroll
        for (int ks = 0; ks < 16; ks++) {
            const int k0b = ks * 32;
            uint32_t af[4];
            ldsm_x4(af, sb + SM_H1 + (r3 + lr)*H1_STRB + k0b + lcb);
            uint32_t bf[2];
            ldsm_x2(bf, sb + SM_WO3 + br_*WO3_STRB + k0b + bcb);
            mma16816(a3, af, bf);
        }
        // a3: c0=(r3+g, 2tg) c1=(r3+g, 2tg+1) c2=(r3+g+8, 2tg) c3=(r3+g+8, 2tg+1)
        float2 bo = *(const float2*)(b_out + tg*2);
        #pragma unroll
        for (int h = 0; h < 2; h++) {
            const int r = r3 + g + h*8;
            const int b = r & 7;
            const int j = j0 + (r >> 3);
            bool m = (mask[b*Ln + i] != 0) && (mask[b*Ln + j] != 0);
            float v0 = a3[2*h + 0] + bo.x;
            float v1 = a3[2*h + 1] + bo.y;
            if (!m) { v0 = -CUDART_INF_F; v1 = -CUDART_INF_F; }
            size_t base = ((size_t)(b*NHo + tg*2))*(Ln*Ln) + (size_t)i*Ln + j;
            out[base]         = v0;
            out[base + Ln*Ln] = v1;
        }
    }
}

// ---------------------------------------------------------------------------
extern "C" void kernel_launch(void* const* d_in, const int* in_sizes, int n_in,
                              void* d_out, int out_size) {
    const float* x     = (const float*)d_in[0];
    const float* dist  = (const float*)d_in[1];
    const int*   mask  = (const int*)d_in[2];
    const float* W_rbf = (const float*)d_in[3];
    const float* b_rbf = (const float*)d_in[4];
    const float* W1    = (const float*)d_in[5];
    const float* W2    = (const float*)d_in[6];
    const float* W3    = (const float*)d_in[7];
    const float* b_in  = (const float*)d_in[8];
    const float* W_res = (const float*)d_in[9];
    const float* b_res = (const float*)d_in[10];
    const float* W_out = (const float*)d_in[11];
    const float* b_out = (const float*)d_in[12];
    float*       out   = (float*)d_out;

    prep_kernel<<<PR_TOT, 256>>>(x, W_rbf, b_rbf, W1, W2, W3, b_in, W_res);

    cudaFuncSetAttribute(pair_kernel, cudaFuncAttributeMaxDynamicSharedMemorySize, SM_TOTAL);
    dim3 grid(Ln / TJ, Ln);
    pair_kernel<<<grid, 256, SM_TOTAL>>>(dist, mask, b_res, W_out, b_out, out);
}